// round 12
// baseline (speedup 1.0000x reference)
#include <cuda_runtime.h>
#include <cstdint>

typedef unsigned long long u64;

#define T_LEN 1024
#define NB    64
#define IDIM  128
#define HID   256
#define GDIM  1024
#define CLS   8

// scratch (device globals: allocation-free)
__device__ float g_pre[(size_t)T_LEN * NB * GDIM];   // [t][b][g]  256 MB
__device__ float g_WihT[IDIM * GDIM];                // [i][g]
__device__ float g_bsum[GDIM];

// ---------------- packed f32x2 helpers ----------------
__device__ __forceinline__ u64 pk2(float lo, float hi) {
    u64 r;
    asm("mov.b64 %0, {%1, %2};" : "=l"(r) : "r"(__float_as_uint(lo)), "r"(__float_as_uint(hi)));
    return r;
}
__device__ __forceinline__ u64 dup2(float x) {
    u64 r;
    asm("mov.b64 %0, {%1, %1};" : "=l"(r) : "r"(__float_as_uint(x)));
    return r;
}
__device__ __forceinline__ void upk2(u64 v, float& lo, float& hi) {
    uint32_t a, b;
    asm("mov.b64 {%0, %1}, %2;" : "=r"(a), "=r"(b) : "l"(v));
    lo = __uint_as_float(a); hi = __uint_as_float(b);
}
__device__ __forceinline__ u64 ffma2(u64 a, u64 b, u64 c) {
    u64 d;
    asm("fma.rn.f32x2 %0, %1, %2, %3;" : "=l"(d) : "l"(a), "l"(b), "l"(c));
    return d;
}
// HW-accelerated activations (sm_103a MUFU tanh)
__device__ __forceinline__ float tanha(float x) {
    float y;
    asm("tanh.approx.f32 %0, %1;" : "=f"(y) : "f"(x));
    return y;
}
__device__ __forceinline__ float fsig(float x) {
    return fmaf(0.5f, tanha(0.5f * x), 0.5f);
}
__device__ __forceinline__ float ftanh(float x) {
    return tanha(x);
}
__device__ __forceinline__ uint32_t smem_u32(const void* p) {
    return (uint32_t)__cvta_generic_to_shared(p);
}
__device__ __forceinline__ void mbar_init(uint32_t a, uint32_t cnt) {
    asm volatile("mbarrier.init.shared.b64 [%0], %1;" :: "r"(a), "r"(cnt) : "memory");
}
__device__ __forceinline__ void mbar_arrive_expect(uint32_t a, uint32_t tx) {
    asm volatile("mbarrier.arrive.expect_tx.shared.b64 _, [%0], %1;" :: "r"(a), "r"(tx) : "memory");
}
// ACTIVE-SPIN wait (single change vs R11): test_wait poll, no HW sleep.
// Keeps the SM busy so DVFS doesn't downclock the latency chain.
__device__ __forceinline__ void mbar_wait(uint32_t a, uint32_t parity) {
    asm volatile("{\n\t.reg .pred P1;\n\t"
        "W_%=:\n\t"
        "mbarrier.test_wait.parity.acquire.cta.shared::cta.b64 P1, [%0], %1;\n\t"
        "@P1 bra.uni D_%=;\n\t"
        "bra.uni W_%=;\n\t"
        "D_%=:\n\t}"
        :: "r"(a), "r"(parity) : "memory");
}
__device__ __forceinline__ void st_async_b64(uint32_t raddr, u64 v, uint32_t rbar) {
    asm volatile("st.async.shared::cluster.mbarrier::complete_tx::bytes.b64 [%0], %1, [%2];"
                 :: "r"(raddr), "l"(v), "r"(rbar) : "memory");
}

// =====================================================================
// Kernel 0: transpose W_ih -> g_WihT[i][g]; bias sum
// =====================================================================
__global__ void prep_kernel(const float* __restrict__ W_ih,
                            const float* __restrict__ b_ih,
                            const float* __restrict__ b_hh) {
    int idx = blockIdx.x * 256 + threadIdx.x;
    int i = idx >> 10;
    int g = idx & 1023;
    g_WihT[idx] = W_ih[g * IDIM + i];
    if (idx < GDIM) g_bsum[idx] = b_ih[idx] + b_hh[idx];
}

// dummy kernel so lstm_rec is the 4th launch (ncu captures launch #4)
__global__ void nudge_kernel() {}

// =====================================================================
// Kernel 1: pre[t][b][g] = sum_i x[b][i][t] * W_ih[g][i] + bsum[g]
// =====================================================================
#define XS_STRIDE 68
#define WS_STRIDE 132
#define SMEM1 ((IDIM * XS_STRIDE + IDIM * WS_STRIDE) * 4)

__global__ __launch_bounds__(256, 2) void gemm_pre(const float* __restrict__ x) {
    extern __shared__ float sm[];
    float* x_s = sm;
    float* w_s = sm + IDIM * XS_STRIDE;

    int tid = threadIdx.x;
    int g0 = blockIdx.x * 128;
    int t0 = blockIdx.y * 64;
    int b  = blockIdx.z;

    const float* xb = x + (size_t)b * IDIM * T_LEN;
    #pragma unroll
    for (int idx = tid; idx < 128 * 16; idx += 256) {
        int i = idx >> 4, c4 = idx & 15;
        float4 v = *(const float4*)(xb + (size_t)i * T_LEN + t0 + 4 * c4);
        *(float4*)(x_s + i * XS_STRIDE + 4 * c4) = v;
    }
    #pragma unroll
    for (int idx = tid; idx < 128 * 32; idx += 256) {
        int i = idx >> 5, c4 = idx & 31;
        float4 v = *(const float4*)(g_WihT + (size_t)i * GDIM + g0 + 4 * c4);
        *(float4*)(w_s + i * WS_STRIDE + 4 * c4) = v;
    }
    __syncthreads();

    int tx = tid & 15;
    int ty = tid >> 4;

    u64 acc[4][4];
    #pragma unroll
    for (int a = 0; a < 4; a++)
        #pragma unroll
        for (int c = 0; c < 4; c++) acc[a][c] = 0ull;

    const float* xp = x_s + 4 * ty;
    const float* wp = w_s + 8 * tx;

    #pragma unroll 4
    for (int k = 0; k < 128; k++) {
        float4 xv = *(const float4*)(xp + k * XS_STRIDE);
        ulonglong2 wa = *(const ulonglong2*)(wp + k * WS_STRIDE);
        ulonglong2 wb = *(const ulonglong2*)(wp + k * WS_STRIDE + 4);
        u64 d0 = dup2(xv.x), d1 = dup2(xv.y), d2 = dup2(xv.z), d3 = dup2(xv.w);
        acc[0][0] = ffma2(d0, wa.x, acc[0][0]);
        acc[0][1] = ffma2(d0, wa.y, acc[0][1]);
        acc[0][2] = ffma2(d0, wb.x, acc[0][2]);
        acc[0][3] = ffma2(d0, wb.y, acc[0][3]);
        acc[1][0] = ffma2(d1, wa.x, acc[1][0]);
        acc[1][1] = ffma2(d1, wa.y, acc[1][1]);
        acc[1][2] = ffma2(d1, wb.x, acc[1][2]);
        acc[1][3] = ffma2(d1, wb.y, acc[1][3]);
        acc[2][0] = ffma2(d2, wa.x, acc[2][0]);
        acc[2][1] = ffma2(d2, wa.y, acc[2][1]);
        acc[2][2] = ffma2(d2, wb.x, acc[2][2]);
        acc[2][3] = ffma2(d2, wb.y, acc[2][3]);
        acc[3][0] = ffma2(d3, wa.x, acc[3][0]);
        acc[3][1] = ffma2(d3, wa.y, acc[3][1]);
        acc[3][2] = ffma2(d3, wb.x, acc[3][2]);
        acc[3][3] = ffma2(d3, wb.y, acc[3][3]);
    }

    float4 bsa = *(const float4*)(g_bsum + g0 + 8 * tx);
    float4 bsb = *(const float4*)(g_bsum + g0 + 8 * tx + 4);

    #pragma unroll
    for (int tt = 0; tt < 4; tt++) {
        float l0, h0, l1, h1, l2, h2, l3, h3;
        upk2(acc[tt][0], l0, h0);
        upk2(acc[tt][1], l1, h1);
        upk2(acc[tt][2], l2, h2);
        upk2(acc[tt][3], l3, h3);
        float4 o1 = make_float4(l0 + bsa.x, h0 + bsa.y, l1 + bsa.z, h1 + bsa.w);
        float4 o2 = make_float4(l2 + bsb.x, h2 + bsb.y, l3 + bsb.z, h3 + bsb.w);
        size_t base = ((size_t)(t0 + 4 * ty + tt) * NB + b) * GDIM + g0 + 8 * tx;
        *(float4*)(g_pre + base)     = o1;
        *(float4*)(g_pre + base + 4) = o2;
    }
}

// =====================================================================
// Kernel 2: recurrence (R11 structure; only the wait loop changed to spin)
// =====================================================================
__global__ __launch_bounds__(512, 1) __cluster_dims__(CLS, 1, 1)
void lstm_rec(const float* __restrict__ W_hh, float* __restrict__ out) {
    __shared__ float h_buf[2][2][2][HID];   // [grp][buf][b2][u] 8KB (offset 0)
    __shared__ float red[2][16 * 133];      // [grp][(b2*8+kq)*133 + l]
    __shared__ float pre_s[2][8 * 36];      // [grp][(gate*2+b2)*36 + u]
    __shared__ u64  mbar[4];                // A0 A1 B0 B1

    int tid  = threadIdx.x;
    int rank = blockIdx.x & (CLS - 1);
    int cid  = blockIdx.x >> 3;
    int w    = tid >> 5, lane = tid & 31;
    int kq   = w >> 1, half = w & 1;

    uint32_t hbase_loc = smem_u32(&h_buf[0][0][0][0]);
    uint32_t bar_loc   = smem_u32(&mbar[0]);

    // ---- W_hh slice -> registers (shared by both groups)
    u64 wreg[2][8][2];
    #pragma unroll
    for (int rr = 0; rr < 2; rr++) {
        int gate = 2 * half + rr;
        int grow = (gate << 8) + (rank << 5) + lane;
        const float* wr = W_hh + (size_t)grow * HID + (kq << 5);
        #pragma unroll
        for (int j = 0; j < 8; j++) {
            float4 v = *(const float4*)(wr + 4 * j);
            wreg[rr][j][0] = pk2(v.x, v.y);
            wreg[rr][j][1] = pk2(v.z, v.w);
        }
    }

    for (int i = tid; i < 2 * 2 * 2 * HID; i += 512) ((float*)h_buf)[i] = 0.0f;
    if (tid == 0) {
        #pragma unroll
        for (int i = 0; i < 4; i++) {
            mbar_init(bar_loc + 8 * i, 1);
            mbar_arrive_expect(bar_loc + 8 * i, 2048);  // 8 CTAs x 32 b64
        }
    }
    __syncthreads();
    asm volatile("barrier.cluster.arrive.aligned;\n\tbarrier.cluster.wait.aligned;" ::: "memory");

    // remote smem bases per rank (mapa affine)
    uint32_t rbase[CLS];
    #pragma unroll
    for (int r = 0; r < CLS; r++)
        asm volatile("mapa.shared::cluster.u32 %0, %1, %2;" : "=r"(rbase[r]) : "r"(hbase_loc), "r"(r));
    uint32_t bar_off = bar_loc - hbase_loc;

    // act roles: warps 0-1 -> group A, warps 2-3 -> group B
    int agrp   = (w >= 2);             // valid for w<4
    int alocal = tid & 63;             // 0..63 within the 2-warp act set
    int au     = alocal >> 1;          // unit 0..31
    int ab2    = alocal & 1;           // batch-in-group
    float c_st = 0.0f;
    float o0 = 0.f, o1 = 0.f, o2 = 0.f, o3 = 0.f;
    size_t out_base = ((size_t)(4 * cid + 2 * agrp + ab2) * HID + (rank << 5) + au) * T_LEN;
    // b64 slot (units au, au+1) within h_buf section [grp][buf][b2]
    uint32_t pair_base = (uint32_t)((ab2 * HID + (rank << 5) + (au & ~1)) << 2);

    // pre prefetch: warp w -> grp = w>>3, chunk c = w&7 (gate=c>>1, b2=c&1)
    int pgrp = w >> 3, pcc = w & 7;
    int pgate = pcc >> 1, pb2 = pcc & 1;
    size_t pre_base = (size_t)(4 * cid + 2 * pgrp + pb2) * GDIM + (pgate << 8) + (rank << 5) + lane;

    uint32_t pA0 = 0, pA1 = 0, pB0 = 0, pB1 = 0;

    for (int t = 0; t < T_LEN; t++) {
        int cur = t & 1, nxt = cur ^ 1;

        float prev = __ldg(g_pre + (size_t)t * (NB * GDIM) + pre_base);

        // ================= group A =================
        if (t > 0) {
            if (cur) { mbar_wait(bar_loc + 8, pA1); pA1 ^= 1; }
            else     { mbar_wait(bar_loc,     pA0); pA0 ^= 1; }
            if (tid == 0) mbar_arrive_expect(bar_loc + 8u * (uint32_t)cur, 2048);
        }
        {
            const float* hb = &h_buf[0][cur][0][0];
            #pragma unroll
            for (int b2 = 0; b2 < 2; b2++) {
                u64 a0 = 0ull, a1 = 0ull;
                const ulonglong2* hp = (const ulonglong2*)(hb + (b2 << 8) + (kq << 5));
                #pragma unroll
                for (int j = 0; j < 8; j++) {
                    ulonglong2 hv = hp[j];
                    a0 = ffma2(hv.x, wreg[0][j][0], a0);
                    a0 = ffma2(hv.y, wreg[0][j][1], a0);
                    a1 = ffma2(hv.x, wreg[1][j][0], a1);
                    a1 = ffma2(hv.y, wreg[1][j][1], a1);
                }
                float lo, hi;
                upk2(a0, lo, hi);
                red[0][(b2 * 8 + kq) * 133 + ((2 * half) << 5) + lane] = lo + hi;
                upk2(a1, lo, hi);
                red[0][(b2 * 8 + kq) * 133 + ((2 * half + 1) << 5) + lane] = lo + hi;
            }
            if (w < 8) pre_s[0][pcc * 36 + lane] = prev;
        }
        if (w >= 2) asm volatile("bar.arrive 1, 512;" ::: "memory");

        // ================= group B =================
        if (t > 0) {
            if (cur) { mbar_wait(bar_loc + 24, pB1); pB1 ^= 1; }
            else     { mbar_wait(bar_loc + 16, pB0); pB0 ^= 1; }
            if (tid == 480) mbar_arrive_expect(bar_loc + 16u + 8u * (uint32_t)cur, 2048);
        }
        {
            const float* hb = &h_buf[1][cur][0][0];
            #pragma unroll
            for (int b2 = 0; b2 < 2; b2++) {
                u64 a0 = 0ull, a1 = 0ull;
                const ulonglong2* hp = (const ulonglong2*)(hb + (b2 << 8) + (kq << 5));
                #pragma unroll
                for (int j = 0; j < 8; j++) {
                    ulonglong2 hv = hp[j];
                    a0 = ffma2(hv.x, wreg[0][j][0], a0);
                    a0 = ffma2(hv.y, wreg[0][j][1], a0);
                    a1 = ffma2(hv.x, wreg[1][j][0], a1);
                    a1 = ffma2(hv.y, wreg[1][j][1], a1);
                }
                float lo, hi;
                upk2(a0, lo, hi);
                red[1][(b2 * 8 + kq) * 133 + ((2 * half) << 5) + lane] = lo + hi;
                upk2(a1, lo, hi);
                red[1][(b2 * 8 + kq) * 133 + ((2 * half + 1) << 5) + lane] = lo + hi;
            }
            if (w >= 8) pre_s[1][pcc * 36 + lane] = prev;
        }

        // ================= act phases =================
        if (w < 4) {
            if (w < 2) asm volatile("bar.sync 1, 512;" ::: "memory");
            else       asm volatile("bar.sync 2, 512;" ::: "memory");
            const float* rd = red[agrp];
            const float* ps = pre_s[agrp];
            float g4[4];
            #pragma unroll
            for (int gate = 0; gate < 4; gate++) {
                int l = (gate << 5) + au;
                float s0 = rd[(ab2 * 8 + 0) * 133 + l] + rd[(ab2 * 8 + 1) * 133 + l];
                float s1 = rd[(ab2 * 8 + 2) * 133 + l] + rd[(ab2 * 8 + 3) * 133 + l];
                float s2 = rd[(ab2 * 8 + 4) * 133 + l] + rd[(ab2 * 8 + 5) * 133 + l];
                float s3 = (rd[(ab2 * 8 + 6) * 133 + l] + rd[(ab2 * 8 + 7) * 133 + l])
                         + ps[((gate << 1) + ab2) * 36 + au];
                g4[gate] = (s0 + s1) + (s2 + s3);
            }
            float ig = fsig(g4[0]), fg = fsig(g4[1]);
            float gg = ftanh(g4[2]), og = fsig(g4[3]);
            c_st = fg * c_st + ig * gg;
            float h = og * ftanh(c_st);

            // push h pair first (critical path)
            float h_up = __shfl_down_sync(0xffffffffu, h, 2);  // h of au+1, same ab2
            if ((au & 1) == 0) {
                u64 hv2 = pk2(h, h_up);
                uint32_t hoff = (uint32_t)(((agrp * 2 + nxt) * 2 * HID) << 2) + pair_base;
                uint32_t boff = bar_off + 8u * (uint32_t)(agrp * 2 + nxt);
                #pragma unroll
                for (int r = 0; r < CLS; r++)
                    st_async_b64(rbase[r] + hoff, hv2, rbase[r] + boff);
            }
            if (w < 2) asm volatile("bar.arrive 2, 512;" ::: "memory");

            float hr = fmaxf(h, 0.0f);
            int ph = t & 3;
            if (ph == 0) o0 = hr; else if (ph == 1) o1 = hr;
            else if (ph == 2) o2 = hr; else o3 = hr;
            if (ph == 3)
                *(float4*)(out + out_base + (t - 3)) = make_float4(o0, o1, o2, o3);
        } else {
            asm volatile("bar.arrive 2, 512;" ::: "memory");
        }
    }
    asm volatile("barrier.cluster.arrive.aligned;\n\tbarrier.cluster.wait.aligned;" ::: "memory");
}

// =====================================================================
extern "C" void kernel_launch(void* const* d_in, const int* in_sizes, int n_in,
                              void* d_out, int out_size) {
    const float* x    = (const float*)d_in[0];
    const float* W_ih = (const float*)d_in[1];
    const float* W_hh = (const float*)d_in[2];
    const float* b_ih = (const float*)d_in[3];
    const float* b_hh = (const float*)d_in[4];
    float* out = (float*)d_out;

    prep_kernel<<<512, 256>>>(W_ih, b_ih, b_hh);                 // launch 1

    cudaFuncSetAttribute(gemm_pre, cudaFuncAttributeMaxDynamicSharedMemorySize, SMEM1);
    dim3 grid1(GDIM / 128, T_LEN / 64, NB);
    gemm_pre<<<grid1, 256, SMEM1>>>(x);                          // launch 2

    nudge_kernel<<<1, 32>>>();                                   // launch 3

    lstm_rec<<<NB / 4 * CLS, 512>>>(W_hh, out);                  // launch 4 (ncu target)
}

// round 13
// speedup vs baseline: 1.0351x; 1.0351x over previous
#include <cuda_runtime.h>
#include <cstdint>

typedef unsigned long long u64;

#define T_LEN 1024
#define NB    64
#define IDIM  128
#define HID   256
#define GDIM  1024
#define CLS   8

// scratch (device globals: allocation-free)
__device__ float g_pre[(size_t)T_LEN * NB * GDIM];   // [t][b][g]  256 MB
__device__ float g_WihT[IDIM * GDIM];                // [i][g]
__device__ float g_bsum[GDIM];

// ---------------- packed f32x2 helpers ----------------
__device__ __forceinline__ u64 pk2(float lo, float hi) {
    u64 r;
    asm("mov.b64 %0, {%1, %2};" : "=l"(r) : "r"(__float_as_uint(lo)), "r"(__float_as_uint(hi)));
    return r;
}
__device__ __forceinline__ u64 dup2(float x) {
    u64 r;
    asm("mov.b64 %0, {%1, %1};" : "=l"(r) : "r"(__float_as_uint(x)));
    return r;
}
__device__ __forceinline__ void upk2(u64 v, float& lo, float& hi) {
    uint32_t a, b;
    asm("mov.b64 {%0, %1}, %2;" : "=r"(a), "=r"(b) : "l"(v));
    lo = __uint_as_float(a); hi = __uint_as_float(b);
}
__device__ __forceinline__ u64 ffma2(u64 a, u64 b, u64 c) {
    u64 d;
    asm("fma.rn.f32x2 %0, %1, %2, %3;" : "=l"(d) : "l"(a), "l"(b), "l"(c));
    return d;
}
// HW-accelerated activations (sm_103a MUFU tanh)
__device__ __forceinline__ float tanha(float x) {
    float y;
    asm("tanh.approx.f32 %0, %1;" : "=f"(y) : "f"(x));
    return y;
}
__device__ __forceinline__ float fsig(float x) {
    return fmaf(0.5f, tanha(0.5f * x), 0.5f);
}
__device__ __forceinline__ float ftanh(float x) {
    return tanha(x);
}
__device__ __forceinline__ uint32_t smem_u32(const void* p) {
    return (uint32_t)__cvta_generic_to_shared(p);
}
__device__ __forceinline__ void mbar_init(uint32_t a, uint32_t cnt) {
    asm volatile("mbarrier.init.shared.b64 [%0], %1;" :: "r"(a), "r"(cnt) : "memory");
}
__device__ __forceinline__ void mbar_arrive_expect(uint32_t a, uint32_t tx) {
    asm volatile("mbarrier.arrive.expect_tx.shared.b64 _, [%0], %1;" :: "r"(a), "r"(tx) : "memory");
}
// R11 sleeping wait (spin regressed in R12 -> reverted)
__device__ __forceinline__ void mbar_wait(uint32_t a, uint32_t parity) {
    uint32_t done;
    asm volatile("{\n\t.reg .pred p;\n\t"
        "mbarrier.try_wait.parity.acquire.cta.shared::cta.b64 p, [%1], %2;\n\t"
        "selp.b32 %0, 1, 0, p;\n\t}"
        : "=r"(done) : "r"(a), "r"(parity) : "memory");
    if (!done) {
        asm volatile("{\n\t.reg .pred P1;\n\t"
            "W_%=:\n\t"
            "mbarrier.try_wait.parity.acquire.cta.shared::cta.b64 P1, [%0], %1, 0x989680;\n\t"
            "@P1 bra.uni D_%=;\n\t"
            "bra.uni W_%=;\n\t"
            "D_%=:\n\t}"
            :: "r"(a), "r"(parity) : "memory");
    }
}
__device__ __forceinline__ void st_async_b64(uint32_t raddr, u64 v, uint32_t rbar) {
    asm volatile("st.async.shared::cluster.mbarrier::complete_tx::bytes.b64 [%0], %1, [%2];"
                 :: "r"(raddr), "l"(v), "r"(rbar) : "memory");
}

// =====================================================================
// Kernel 0: transpose W_ih -> g_WihT[i][g]; bias sum
// =====================================================================
__global__ void prep_kernel(const float* __restrict__ W_ih,
                            const float* __restrict__ b_ih,
                            const float* __restrict__ b_hh) {
    int idx = blockIdx.x * 256 + threadIdx.x;
    int i = idx >> 10;
    int g = idx & 1023;
    g_WihT[idx] = W_ih[g * IDIM + i];
    if (idx < GDIM) g_bsum[idx] = b_ih[idx] + b_hh[idx];
}

// dummy kernel so lstm_rec is the 4th launch (ncu captures launch #4)
__global__ void nudge_kernel() {}

// =====================================================================
// Kernel 1: pre[t][b][g] = sum_i x[b][i][t] * W_ih[g][i] + bsum[g]
// =====================================================================
#define XS_STRIDE 68
#define WS_STRIDE 132
#define SMEM1 ((IDIM * XS_STRIDE + IDIM * WS_STRIDE) * 4)

__global__ __launch_bounds__(256, 2) void gemm_pre(const float* __restrict__ x) {
    extern __shared__ float sm[];
    float* x_s = sm;
    float* w_s = sm + IDIM * XS_STRIDE;

    int tid = threadIdx.x;
    int g0 = blockIdx.x * 128;
    int t0 = blockIdx.y * 64;
    int b  = blockIdx.z;

    const float* xb = x + (size_t)b * IDIM * T_LEN;
    #pragma unroll
    for (int idx = tid; idx < 128 * 16; idx += 256) {
        int i = idx >> 4, c4 = idx & 15;
        float4 v = *(const float4*)(xb + (size_t)i * T_LEN + t0 + 4 * c4);
        *(float4*)(x_s + i * XS_STRIDE + 4 * c4) = v;
    }
    #pragma unroll
    for (int idx = tid; idx < 128 * 32; idx += 256) {
        int i = idx >> 5, c4 = idx & 31;
        float4 v = *(const float4*)(g_WihT + (size_t)i * GDIM + g0 + 4 * c4);
        *(float4*)(w_s + i * WS_STRIDE + 4 * c4) = v;
    }
    __syncthreads();

    int tx = tid & 15;
    int ty = tid >> 4;

    u64 acc[4][4];
    #pragma unroll
    for (int a = 0; a < 4; a++)
        #pragma unroll
        for (int c = 0; c < 4; c++) acc[a][c] = 0ull;

    const float* xp = x_s + 4 * ty;
    const float* wp = w_s + 8 * tx;

    #pragma unroll 4
    for (int k = 0; k < 128; k++) {
        float4 xv = *(const float4*)(xp + k * XS_STRIDE);
        ulonglong2 wa = *(const ulonglong2*)(wp + k * WS_STRIDE);
        ulonglong2 wb = *(const ulonglong2*)(wp + k * WS_STRIDE + 4);
        u64 d0 = dup2(xv.x), d1 = dup2(xv.y), d2 = dup2(xv.z), d3 = dup2(xv.w);
        acc[0][0] = ffma2(d0, wa.x, acc[0][0]);
        acc[0][1] = ffma2(d0, wa.y, acc[0][1]);
        acc[0][2] = ffma2(d0, wb.x, acc[0][2]);
        acc[0][3] = ffma2(d0, wb.y, acc[0][3]);
        acc[1][0] = ffma2(d1, wa.x, acc[1][0]);
        acc[1][1] = ffma2(d1, wa.y, acc[1][1]);
        acc[1][2] = ffma2(d1, wb.x, acc[1][2]);
        acc[1][3] = ffma2(d1, wb.y, acc[1][3]);
        acc[2][0] = ffma2(d2, wa.x, acc[2][0]);
        acc[2][1] = ffma2(d2, wa.y, acc[2][1]);
        acc[2][2] = ffma2(d2, wb.x, acc[2][2]);
        acc[2][3] = ffma2(d2, wb.y, acc[2][3]);
        acc[3][0] = ffma2(d3, wa.x, acc[3][0]);
        acc[3][1] = ffma2(d3, wa.y, acc[3][1]);
        acc[3][2] = ffma2(d3, wb.x, acc[3][2]);
        acc[3][3] = ffma2(d3, wb.y, acc[3][3]);
    }

    float4 bsa = *(const float4*)(g_bsum + g0 + 8 * tx);
    float4 bsb = *(const float4*)(g_bsum + g0 + 8 * tx + 4);

    #pragma unroll
    for (int tt = 0; tt < 4; tt++) {
        float l0, h0, l1, h1, l2, h2, l3, h3;
        upk2(acc[tt][0], l0, h0);
        upk2(acc[tt][1], l1, h1);
        upk2(acc[tt][2], l2, h2);
        upk2(acc[tt][3], l3, h3);
        float4 o1 = make_float4(l0 + bsa.x, h0 + bsa.y, l1 + bsa.z, h1 + bsa.w);
        float4 o2 = make_float4(l2 + bsb.x, h2 + bsb.y, l3 + bsb.z, h3 + bsb.w);
        size_t base = ((size_t)(t0 + 4 * ty + tt) * NB + b) * GDIM + g0 + 8 * tx;
        *(float4*)(g_pre + base)     = o1;
        *(float4*)(g_pre + base + 4) = o2;
    }
}

// =====================================================================
// Kernel 2: recurrence (R11 structure + one-iteration LDG prefetch pipeline)
// =====================================================================
__global__ __launch_bounds__(512, 1) __cluster_dims__(CLS, 1, 1)
void lstm_rec(const float* __restrict__ W_hh, float* __restrict__ out) {
    __shared__ float h_buf[2][2][2][HID];   // [grp][buf][b2][u] 8KB (offset 0)
    __shared__ float red[2][16 * 133];      // [grp][(b2*8+kq)*133 + l]
    __shared__ float pre_s[2][8 * 36];      // [grp][(gate*2+b2)*36 + u]
    __shared__ u64  mbar[4];                // A0 A1 B0 B1

    int tid  = threadIdx.x;
    int rank = blockIdx.x & (CLS - 1);
    int cid  = blockIdx.x >> 3;
    int w    = tid >> 5, lane = tid & 31;
    int kq   = w >> 1, half = w & 1;

    uint32_t hbase_loc = smem_u32(&h_buf[0][0][0][0]);
    uint32_t bar_loc   = smem_u32(&mbar[0]);

    // ---- W_hh slice -> registers (shared by both groups)
    u64 wreg[2][8][2];
    #pragma unroll
    for (int rr = 0; rr < 2; rr++) {
        int gate = 2 * half + rr;
        int grow = (gate << 8) + (rank << 5) + lane;
        const float* wr = W_hh + (size_t)grow * HID + (kq << 5);
        #pragma unroll
        for (int j = 0; j < 8; j++) {
            float4 v = *(const float4*)(wr + 4 * j);
            wreg[rr][j][0] = pk2(v.x, v.y);
            wreg[rr][j][1] = pk2(v.z, v.w);
        }
    }

    for (int i = tid; i < 2 * 2 * 2 * HID; i += 512) ((float*)h_buf)[i] = 0.0f;
    if (tid == 0) {
        #pragma unroll
        for (int i = 0; i < 4; i++) {
            mbar_init(bar_loc + 8 * i, 1);
            mbar_arrive_expect(bar_loc + 8 * i, 2048);  // 8 CTAs x 32 b64
        }
    }
    __syncthreads();
    asm volatile("barrier.cluster.arrive.aligned;\n\tbarrier.cluster.wait.aligned;" ::: "memory");

    // remote smem bases per rank (mapa affine)
    uint32_t rbase[CLS];
    #pragma unroll
    for (int r = 0; r < CLS; r++)
        asm volatile("mapa.shared::cluster.u32 %0, %1, %2;" : "=r"(rbase[r]) : "r"(hbase_loc), "r"(r));
    uint32_t bar_off = bar_loc - hbase_loc;

    // act roles: warps 0-1 -> group A, warps 2-3 -> group B
    int agrp   = (w >= 2);             // valid for w<4
    int alocal = tid & 63;             // 0..63 within the 2-warp act set
    int au     = alocal >> 1;          // unit 0..31
    int ab2    = alocal & 1;           // batch-in-group
    float c_st = 0.0f;
    float o0 = 0.f, o1 = 0.f, o2 = 0.f, o3 = 0.f;
    size_t out_base = ((size_t)(4 * cid + 2 * agrp + ab2) * HID + (rank << 5) + au) * T_LEN;
    // b64 slot (units au, au+1) within h_buf section [grp][buf][b2]
    uint32_t pair_base = (uint32_t)((ab2 * HID + (rank << 5) + (au & ~1)) << 2);

    // pre prefetch: warp w -> grp = w>>3, chunk c = w&7 (gate=c>>1, b2=c&1)
    int pgrp = w >> 3, pcc = w & 7;
    int pgate = pcc >> 1, pb2 = pcc & 1;
    size_t pre_base = (size_t)(4 * cid + 2 * pgrp + pb2) * GDIM + (pgate << 8) + (rank << 5) + lane;

    uint32_t pA0 = 0, pA1 = 0, pB0 = 0, pB1 = 0;

    // SW pipeline: prev holds pre[t]; load for t+1 issues at top of iter t.
    float prev = __ldg(g_pre + pre_base);   // t = 0

    for (int t = 0; t < T_LEN; t++) {
        int cur = t & 1, nxt = cur ^ 1;

        // issue next step's load NOW — full step to hide DRAM latency
        int tn = (t + 1 < T_LEN) ? (t + 1) : t;
        float nxt_pre = __ldg(g_pre + (size_t)tn * (NB * GDIM) + pre_base);

        // ================= group A =================
        if (t > 0) {
            if (cur) { mbar_wait(bar_loc + 8, pA1); pA1 ^= 1; }
            else     { mbar_wait(bar_loc,     pA0); pA0 ^= 1; }
            if (tid == 0) mbar_arrive_expect(bar_loc + 8u * (uint32_t)cur, 2048);
        }
        {
            const float* hb = &h_buf[0][cur][0][0];
            #pragma unroll
            for (int b2 = 0; b2 < 2; b2++) {
                u64 a0 = 0ull, a1 = 0ull;
                const ulonglong2* hp = (const ulonglong2*)(hb + (b2 << 8) + (kq << 5));
                #pragma unroll
                for (int j = 0; j < 8; j++) {
                    ulonglong2 hv = hp[j];
                    a0 = ffma2(hv.x, wreg[0][j][0], a0);
                    a0 = ffma2(hv.y, wreg[0][j][1], a0);
                    a1 = ffma2(hv.x, wreg[1][j][0], a1);
                    a1 = ffma2(hv.y, wreg[1][j][1], a1);
                }
                float lo, hi;
                upk2(a0, lo, hi);
                red[0][(b2 * 8 + kq) * 133 + ((2 * half) << 5) + lane] = lo + hi;
                upk2(a1, lo, hi);
                red[0][(b2 * 8 + kq) * 133 + ((2 * half + 1) << 5) + lane] = lo + hi;
            }
            if (w < 8) pre_s[0][pcc * 36 + lane] = prev;   // register-held, no stall
        }
        if (w >= 2) asm volatile("bar.arrive 1, 512;" ::: "memory");

        // ================= group B =================
        if (t > 0) {
            if (cur) { mbar_wait(bar_loc + 24, pB1); pB1 ^= 1; }
            else     { mbar_wait(bar_loc + 16, pB0); pB0 ^= 1; }
            if (tid == 480) mbar_arrive_expect(bar_loc + 16u + 8u * (uint32_t)cur, 2048);
        }
        {
            const float* hb = &h_buf[1][cur][0][0];
            #pragma unroll
            for (int b2 = 0; b2 < 2; b2++) {
                u64 a0 = 0ull, a1 = 0ull;
                const ulonglong2* hp = (const ulonglong2*)(hb + (b2 << 8) + (kq << 5));
                #pragma unroll
                for (int j = 0; j < 8; j++) {
                    ulonglong2 hv = hp[j];
                    a0 = ffma2(hv.x, wreg[0][j][0], a0);
                    a0 = ffma2(hv.y, wreg[0][j][1], a0);
                    a1 = ffma2(hv.x, wreg[1][j][0], a1);
                    a1 = ffma2(hv.y, wreg[1][j][1], a1);
                }
                float lo, hi;
                upk2(a0, lo, hi);
                red[1][(b2 * 8 + kq) * 133 + ((2 * half) << 5) + lane] = lo + hi;
                upk2(a1, lo, hi);
                red[1][(b2 * 8 + kq) * 133 + ((2 * half + 1) << 5) + lane] = lo + hi;
            }
            if (w >= 8) pre_s[1][pcc * 36 + lane] = prev;  // register-held, no stall
        }

        // ================= act phases =================
        if (w < 4) {
            if (w < 2) asm volatile("bar.sync 1, 512;" ::: "memory");
            else       asm volatile("bar.sync 2, 512;" ::: "memory");
            const float* rd = red[agrp];
            const float* ps = pre_s[agrp];
            float g4[4];
            #pragma unroll
            for (int gate = 0; gate < 4; gate++) {
                int l = (gate << 5) + au;
                float s0 = rd[(ab2 * 8 + 0) * 133 + l] + rd[(ab2 * 8 + 1) * 133 + l];
                float s1 = rd[(ab2 * 8 + 2) * 133 + l] + rd[(ab2 * 8 + 3) * 133 + l];
                float s2 = rd[(ab2 * 8 + 4) * 133 + l] + rd[(ab2 * 8 + 5) * 133 + l];
                float s3 = (rd[(ab2 * 8 + 6) * 133 + l] + rd[(ab2 * 8 + 7) * 133 + l])
                         + ps[((gate << 1) + ab2) * 36 + au];
                g4[gate] = (s0 + s1) + (s2 + s3);
            }
            float ig = fsig(g4[0]), fg = fsig(g4[1]);
            float gg = ftanh(g4[2]), og = fsig(g4[3]);
            c_st = fg * c_st + ig * gg;
            float h = og * ftanh(c_st);

            // push h pair first (critical path)
            float h_up = __shfl_down_sync(0xffffffffu, h, 2);  // h of au+1, same ab2
            if ((au & 1) == 0) {
                u64 hv2 = pk2(h, h_up);
                uint32_t hoff = (uint32_t)(((agrp * 2 + nxt) * 2 * HID) << 2) + pair_base;
                uint32_t boff = bar_off + 8u * (uint32_t)(agrp * 2 + nxt);
                #pragma unroll
                for (int r = 0; r < CLS; r++)
                    st_async_b64(rbase[r] + hoff, hv2, rbase[r] + boff);
            }
            if (w < 2) asm volatile("bar.arrive 2, 512;" ::: "memory");

            float hr = fmaxf(h, 0.0f);
            int ph = t & 3;
            if (ph == 0) o0 = hr; else if (ph == 1) o1 = hr;
            else if (ph == 2) o2 = hr; else o3 = hr;
            if (ph == 3)
                *(float4*)(out + out_base + (t - 3)) = make_float4(o0, o1, o2, o3);
        } else {
            asm volatile("bar.arrive 2, 512;" ::: "memory");
        }

        prev = nxt_pre;
    }
    asm volatile("barrier.cluster.arrive.aligned;\n\tbarrier.cluster.wait.aligned;" ::: "memory");
}

// =====================================================================
extern "C" void kernel_launch(void* const* d_in, const int* in_sizes, int n_in,
                              void* d_out, int out_size) {
    const float* x    = (const float*)d_in[0];
    const float* W_ih = (const float*)d_in[1];
    const float* W_hh = (const float*)d_in[2];
    const float* b_ih = (const float*)d_in[3];
    const float* b_hh = (const float*)d_in[4];
    float* out = (float*)d_out;

    prep_kernel<<<512, 256>>>(W_ih, b_ih, b_hh);                 // launch 1

    cudaFuncSetAttribute(gemm_pre, cudaFuncAttributeMaxDynamicSharedMemorySize, SMEM1);
    dim3 grid1(GDIM / 128, T_LEN / 64, NB);
    gemm_pre<<<grid1, 256, SMEM1>>>(x);                          // launch 2

    nudge_kernel<<<1, 32>>>();                                   // launch 3

    lstm_rec<<<NB / 4 * CLS, 512>>>(W_hh, out);                  // launch 4 (ncu target)
}